// round 6
// baseline (speedup 1.0000x reference)
#include <cuda_runtime.h>
#include <cuda_bf16.h>

#define HH 2048
#define WW 2048

// Cosine matrix C[f][p] = cos((2p+1)*f*pi/16), hard-coded so the fully
// unrolled IDCT passes compile to FFMA-with-immediate (no LDS in the passes).
__device__ constexpr float CM[8][8] = {
  { 1.0f,         1.0f,         1.0f,         1.0f,         1.0f,         1.0f,         1.0f,         1.0f        },
  { 0.98078528f,  0.83146961f,  0.55557023f,  0.19509032f, -0.19509032f, -0.55557023f, -0.83146961f, -0.98078528f },
  { 0.92387953f,  0.38268343f, -0.38268343f, -0.92387953f, -0.92387953f, -0.38268343f,  0.38268343f,  0.92387953f },
  { 0.83146961f, -0.19509032f, -0.98078528f, -0.55557023f,  0.55557023f,  0.98078528f,  0.19509032f, -0.83146961f },
  { 0.70710678f, -0.70710678f, -0.70710678f,  0.70710678f,  0.70710678f, -0.70710678f, -0.70710678f,  0.70710678f },
  { 0.55557023f, -0.98078528f,  0.19509032f,  0.83146961f, -0.83146961f, -0.19509032f,  0.98078528f, -0.55557023f },
  { 0.38268343f, -0.92387953f,  0.92387953f, -0.38268343f, -0.38268343f,  0.92387953f, -0.92387953f,  0.38268343f },
  { 0.19509032f, -0.55557023f,  0.83146961f, -0.98078528f,  0.98078528f, -0.83146961f,  0.55557023f, -0.19509032f },
};

// One CTA = one 32x32 RGB tile. 24 blocks (16Y+4Cb+4Cr); threads 0..191 own
// one 8-float row each. Register-resident IDCT passes; planar pixel buffers
// (Y stride 32, chroma stride 18 — both conflict-free) feed a vectorized
// streaming epilogue. Only two barriers; 32-bit addressing throughout.
__global__ __launch_bounds__(256) void jpeg_decode_kernel(
    const float* __restrict__ ycoef, const float* __restrict__ cbcoef,
    const float* __restrict__ crcoef,
    const float* __restrict__ y_table, const float* __restrict__ c_table,
    const float* __restrict__ alpha, const float* __restrict__ shift,
    const float* __restrict__ matrix, const int* __restrict__ factor_i,
    float* __restrict__ out)
{
    __shared__ float sM[9];         // matrix / 255  (sM[c*3+d])
    __shared__ float sK[3];         // folded constants per output channel
    __shared__ float sT[1728];      // transpose buffer, 24 * 72
    __shared__ float sPY[32 * 32];  // planar Y (raw idct, no +128)
    __shared__ float sPCb[16 * 18];
    __shared__ float sPCr[16 * 18];

    const int tid = threadIdx.x;
    const unsigned tx = blockIdx.x, ty = blockIdx.y, bz = blockIdx.z;
    const unsigned Wb8 = WW / 8, Wb16 = WW / 16;
    const unsigned nY = (HH / 8) * (WW / 8);
    const unsigned nC = (HH / 16) * (WW / 16);

    int fbits = factor_i[0];
    float fac = (fbits > 0 && fbits < (1 << 23)) ? (float)fbits
                                                 : __int_as_float(fbits);
    const float facq = fac * 0.25f;

    if (tid >= 192 && tid < 201) {
        sM[tid - 192] = matrix[tid - 192] * (1.0f / 255.0f);
    } else if (tid >= 201 && tid < 204) {
        // const_d = sum_c (128 + shift[c]) * matrix[c*3+d] / 255
        int d = tid - 201;
        float k = 0.0f;
#pragma unroll
        for (int c = 0; c < 3; c++)
            k = fmaf(128.0f + shift[c], matrix[c * 3 + d], k);
        sK[d] = k * (1.0f / 255.0f);
    }

    const int q = tid >> 3;
    const int x = tid & 7;

    if (tid < 192) {
        const float* src;
        const float* tab;
        unsigned n;
        if (q < 16) {                       // Y blocks: 4x4 arrangement
            int i = q >> 2, j = q & 3;
            n = bz * nY + (ty * 4 + i) * Wb8 + (tx * 4 + j);
            src = ycoef;  tab = y_table;
        } else if (q < 20) {                // Cb blocks: 2x2
            int i = (q - 16) >> 1, j = q & 1;
            n = bz * nC + (ty * 2 + i) * Wb16 + (tx * 2 + j);
            src = cbcoef; tab = c_table;
        } else {                            // Cr blocks: 2x2
            int i = (q - 20) >> 1, j = q & 1;
            n = bz * nC + (ty * 2 + i) * Wb16 + (tx * 2 + j);
            src = crcoef; tab = c_table;
        }
        const float4* g = (const float4*)(src + (size_t)n * 64 + x * 8);
        float4 ra = __ldcs(&g[0]);
        float4 rb = __ldcs(&g[1]);

        // dequant scales straight from gmem (tiny, L1-cached broadcast)
        const float4* t4 = (const float4*)(tab + x * 8);
        const float4* a4 = (const float4*)(alpha + x * 8);
        float4 t0 = __ldg(&t4[0]), t1 = __ldg(&t4[1]);
        float4 A0 = __ldg(&a4[0]), A1 = __ldg(&a4[1]);

        float a0 = ra.x * (t0.x * A0.x * facq);
        float a1 = ra.y * (t0.y * A0.y * facq);
        float a2 = ra.z * (t0.z * A0.z * facq);
        float a3 = ra.w * (t0.w * A0.w * facq);
        float a4v = rb.x * (t1.x * A1.x * facq);
        float a5 = rb.y * (t1.y * A1.y * facq);
        float a6 = rb.z * (t1.z * A1.z * facq);
        float a7 = rb.w * (t1.w * A1.w * facq);

        // pass 1 (over y), all-immediate FMAs: t[v] = sum_y a[y]*CM[y][v]
        float* d = &sT[q * 72 + x * 9];
#pragma unroll
        for (int v = 0; v < 8; v++) {
            float acc = a0 * CM[0][v];
            acc = fmaf(a1, CM[1][v], acc);
            acc = fmaf(a2, CM[2][v], acc);
            acc = fmaf(a3, CM[3][v], acc);
            acc = fmaf(a4v, CM[4][v], acc);
            acc = fmaf(a5, CM[5][v], acc);
            acc = fmaf(a6, CM[6][v], acc);
            acc = fmaf(a7, CM[7][v], acc);
            d[v] = acc;
        }
    }
    __syncthreads();

    if (tid < 192) {
        const int v = x;  // this thread owns column v of block q
        float c0 = sT[q * 72 + 0 * 9 + v];
        float c1 = sT[q * 72 + 1 * 9 + v];
        float c2 = sT[q * 72 + 2 * 9 + v];
        float c3 = sT[q * 72 + 3 * 9 + v];
        float c4 = sT[q * 72 + 4 * 9 + v];
        float c5 = sT[q * 72 + 5 * 9 + v];
        float c6 = sT[q * 72 + 6 * 9 + v];
        float c7 = sT[q * 72 + 7 * 9 + v];

        // destination: planar buffer + stride, by block type
        float* dst;
        int stride;
        if (q < 16) {
            dst = &sPY[((q >> 2) * 8) * 32 + (q & 3) * 8 + v];
            stride = 32;
        } else if (q < 20) {
            int b = q - 16;
            dst = &sPCb[((b >> 1) * 8) * 18 + (b & 1) * 8 + v];
            stride = 18;
        } else {
            int b = q - 20;
            dst = &sPCr[((b >> 1) * 8) * 18 + (b & 1) * 8 + v];
            stride = 18;
        }

        // pass 2 (over x): raw idct values (level shift folded into epilogue)
#pragma unroll
        for (int u = 0; u < 8; u++) {
            float acc = c0 * CM[0][u];
            acc = fmaf(c1, CM[1][u], acc);
            acc = fmaf(c2, CM[2][u], acc);
            acc = fmaf(c3, CM[3][u], acc);
            acc = fmaf(c4, CM[4][u], acc);
            acc = fmaf(c5, CM[5][u], acc);
            acc = fmaf(c6, CM[6][u], acc);
            acc = fmaf(c7, CM[7][u], acc);
            dst[u * stride] = acc;
        }
    }
    __syncthreads();

    // ---- epilogue: 4 px per thread, vectorized LDS, folded transform ----
    const int py = tid >> 3;           // 0..31
    const int px0 = (tid & 7) * 4;     // 0,4,...,28

    const float M0 = sM[0], M1 = sM[1], M2 = sM[2];
    const float M3 = sM[3], M4 = sM[4], M5 = sM[5];
    const float M6 = sM[6], M7 = sM[7], M8 = sM[8];
    const float K0 = sK[0], K1 = sK[1], K2 = sK[2];

    const int cy = py >> 1, cxb = px0 >> 1;
    float2 cbv = *(const float2*)&sPCb[cy * 18 + cxb];
    float2 crv = *(const float2*)&sPCr[cy * 18 + cxb];
    float4 yv = *(const float4*)&sPY[py * 32 + px0];

    float bR[2], bG[2], bB[2];
    {
        bR[0] = fmaf(cbv.x, M3, fmaf(crv.x, M6, K0));
        bG[0] = fmaf(cbv.x, M4, fmaf(crv.x, M7, K1));
        bB[0] = fmaf(cbv.x, M5, fmaf(crv.x, M8, K2));
        bR[1] = fmaf(cbv.y, M3, fmaf(crv.y, M6, K0));
        bG[1] = fmaf(cbv.y, M4, fmaf(crv.y, M7, K1));
        bB[1] = fmaf(cbv.y, M5, fmaf(crv.y, M8, K2));
    }

    float4 oR, oG, oB;
    oR.x = __saturatef(fmaf(yv.x, M0, bR[0]));
    oG.x = __saturatef(fmaf(yv.x, M1, bG[0]));
    oB.x = __saturatef(fmaf(yv.x, M2, bB[0]));
    oR.y = __saturatef(fmaf(yv.y, M0, bR[0]));
    oG.y = __saturatef(fmaf(yv.y, M1, bG[0]));
    oB.y = __saturatef(fmaf(yv.y, M2, bB[0]));
    oR.z = __saturatef(fmaf(yv.z, M0, bR[1]));
    oG.z = __saturatef(fmaf(yv.z, M1, bG[1]));
    oB.z = __saturatef(fmaf(yv.z, M2, bB[1]));
    oR.w = __saturatef(fmaf(yv.w, M0, bR[1]));
    oG.w = __saturatef(fmaf(yv.w, M1, bG[1]));
    oB.w = __saturatef(fmaf(yv.w, M2, bB[1]));

    const unsigned gy = ty * 32 + py;
    const unsigned gx = tx * 32 + px0;
    const unsigned planeOff = gy * WW + gx;          // fits in u32
    const unsigned base = bz * 3u * (HH * WW);
    __stcs((float4*)(out + base + planeOff), oR);
    __stcs((float4*)(out + base + (HH * WW) + planeOff), oG);
    __stcs((float4*)(out + base + 2u * (HH * WW) + planeOff), oB);
}

extern "C" void kernel_launch(void* const* d_in, const int* in_sizes, int n_in,
                              void* d_out, int out_size) {
    const float* y      = (const float*)d_in[0];
    const float* cb     = (const float*)d_in[1];
    const float* cr     = (const float*)d_in[2];
    const float* ytab   = (const float*)d_in[3];
    const float* ctab   = (const float*)d_in[4];
    const float* alpha  = (const float*)d_in[5];
    // d_in[6] = dct_tensor (unused; cosine basis hard-coded)
    const float* shift  = (const float*)d_in[7];
    const float* matrix = (const float*)d_in[8];
    const int* factor   = (const int*)d_in[11];

    int B = in_sizes[0] / (2048 * 2048);
    if (B < 1) B = 1;

    dim3 grid(WW / 32, HH / 32, B);
    jpeg_decode_kernel<<<grid, 256>>>(y, cb, cr, ytab, ctab, alpha, shift,
                                      matrix, factor, (float*)d_out);
}

// round 7
// speedup vs baseline: 1.4750x; 1.4750x over previous
#include <cuda_runtime.h>
#include <cuda_bf16.h>

#define HH 2048
#define WW 2048

// Cosine matrix C[f][p] = cos((2p+1)*f*pi/16), hard-coded so the fully
// unrolled IDCT passes compile to FFMA-with-immediate (no LDS in the passes).
__device__ constexpr float CM[8][8] = {
  { 1.0f,         1.0f,         1.0f,         1.0f,         1.0f,         1.0f,         1.0f,         1.0f        },
  { 0.98078528f,  0.83146961f,  0.55557023f,  0.19509032f, -0.19509032f, -0.55557023f, -0.83146961f, -0.98078528f },
  { 0.92387953f,  0.38268343f, -0.38268343f, -0.92387953f, -0.92387953f, -0.38268343f,  0.38268343f,  0.92387953f },
  { 0.83146961f, -0.19509032f, -0.98078528f, -0.55557023f,  0.55557023f,  0.98078528f,  0.19509032f, -0.83146961f },
  { 0.70710678f, -0.70710678f, -0.70710678f,  0.70710678f,  0.70710678f, -0.70710678f, -0.70710678f,  0.70710678f },
  { 0.55557023f, -0.98078528f,  0.19509032f,  0.83146961f, -0.83146961f, -0.19509032f,  0.98078528f, -0.55557023f },
  { 0.38268343f, -0.92387953f,  0.92387953f, -0.38268343f, -0.38268343f,  0.92387953f, -0.92387953f,  0.38268343f },
  { 0.19509032f, -0.55557023f,  0.83146961f, -0.98078528f,  0.98078528f, -0.83146961f,  0.55557023f, -0.19509032f },
};

// One CTA = one 32x32 RGB tile. 24 blocks (16Y+4Cb+4Cr); threads 0..191 own
// one 8-float row each. Dequant scales staged ONCE per CTA into smem (sD);
// register-resident IDCT passes; planar pixel buffers (Y stride 32, chroma
// stride 18, conflict-free) feed a vectorized streaming epilogue.
__global__ __launch_bounds__(256) void jpeg_decode_kernel(
    const float* __restrict__ ycoef, const float* __restrict__ cbcoef,
    const float* __restrict__ crcoef,
    const float* __restrict__ y_table, const float* __restrict__ c_table,
    const float* __restrict__ alpha, const float* __restrict__ shift,
    const float* __restrict__ matrix, const int* __restrict__ factor_i,
    float* __restrict__ out)
{
    __shared__ float sD[128];       // dequant scale: [0:64) Y, [64:128) chroma
    __shared__ float sM[9];         // matrix / 255  (sM[c*3+d])
    __shared__ float sK[3];         // folded constants per output channel
    __shared__ float sT[1728];      // transpose buffer, 24 * 72
    __shared__ float sPY[32 * 32];  // planar Y (raw idct, no +128)
    __shared__ float sPCb[16 * 18];
    __shared__ float sPCr[16 * 18];

    const int tid = threadIdx.x;
    const unsigned tx = blockIdx.x, ty = blockIdx.y, bz = blockIdx.z;
    const unsigned Wb8 = WW / 8, Wb16 = WW / 16;
    const unsigned nY = (HH / 8) * (WW / 8);
    const unsigned nC = (HH / 16) * (WW / 16);

    int fbits = factor_i[0];
    float fac = (fbits > 0 && fbits < (1 << 23)) ? (float)fbits
                                                 : __int_as_float(fbits);

    if (tid < 128) {
        const float* tab = (tid < 64) ? y_table : c_table;
        int o = tid & 63;
        sD[tid] = tab[o] * alpha[o] * fac * 0.25f;
    } else if (tid < 137) {
        sM[tid - 128] = matrix[tid - 128] * (1.0f / 255.0f);
    } else if (tid < 140) {
        // const_d = sum_c (128 + shift[c]) * matrix[c*3+d] / 255
        int d = tid - 137;
        float k = 0.0f;
#pragma unroll
        for (int c = 0; c < 3; c++)
            k = fmaf(128.0f + shift[c], matrix[c * 3 + d], k);
        sK[d] = k * (1.0f / 255.0f);
    }

    const int q = tid >> 3;
    const int x = tid & 7;

    float4 ra, rb;
    if (tid < 192) {
        const float* src;
        unsigned n;
        if (q < 16) {                       // Y blocks: 4x4 arrangement
            int i = q >> 2, j = q & 3;
            n = bz * nY + (ty * 4 + i) * Wb8 + (tx * 4 + j);
            src = ycoef;
        } else if (q < 20) {                // Cb blocks: 2x2
            int i = (q - 16) >> 1, j = q & 1;
            n = bz * nC + (ty * 2 + i) * Wb16 + (tx * 2 + j);
            src = cbcoef;
        } else {                            // Cr blocks: 2x2
            int i = (q - 20) >> 1, j = q & 1;
            n = bz * nC + (ty * 2 + i) * Wb16 + (tx * 2 + j);
            src = crcoef;
        }
        const float4* g = (const float4*)(src + (size_t)n * 64 + x * 8);
        ra = __ldcs(&g[0]);
        rb = __ldcs(&g[1]);
    }
    __syncthreads();

    if (tid < 192) {
        // dequant (scale row from smem, broadcast-friendly)
        const int db = (q < 16 ? 0 : 64) + x * 8;
        float4 da = *(const float4*)&sD[db];
        float4 db4 = *(const float4*)&sD[db + 4];
        float a0 = ra.x * da.x, a1 = ra.y * da.y, a2 = ra.z * da.z, a3 = ra.w * da.w;
        float a4 = rb.x * db4.x, a5 = rb.y * db4.y, a6 = rb.z * db4.z, a7 = rb.w * db4.w;

        // pass 1 (over y), all-immediate FMAs: t[v] = sum_y a[y]*CM[y][v]
        float* d = &sT[q * 72 + x * 9];
#pragma unroll
        for (int v = 0; v < 8; v++) {
            float acc = a0 * CM[0][v];
            acc = fmaf(a1, CM[1][v], acc);
            acc = fmaf(a2, CM[2][v], acc);
            acc = fmaf(a3, CM[3][v], acc);
            acc = fmaf(a4, CM[4][v], acc);
            acc = fmaf(a5, CM[5][v], acc);
            acc = fmaf(a6, CM[6][v], acc);
            acc = fmaf(a7, CM[7][v], acc);
            d[v] = acc;
        }
    }
    __syncthreads();

    if (tid < 192) {
        const int v = x;  // this thread owns column v of block q
        float c0 = sT[q * 72 + 0 * 9 + v];
        float c1 = sT[q * 72 + 1 * 9 + v];
        float c2 = sT[q * 72 + 2 * 9 + v];
        float c3 = sT[q * 72 + 3 * 9 + v];
        float c4 = sT[q * 72 + 4 * 9 + v];
        float c5 = sT[q * 72 + 5 * 9 + v];
        float c6 = sT[q * 72 + 6 * 9 + v];
        float c7 = sT[q * 72 + 7 * 9 + v];

        // destination: planar buffer + stride, by block type
        float* dst;
        int stride;
        if (q < 16) {
            dst = &sPY[((q >> 2) * 8) * 32 + (q & 3) * 8 + v];
            stride = 32;
        } else if (q < 20) {
            int b = q - 16;
            dst = &sPCb[((b >> 1) * 8) * 18 + (b & 1) * 8 + v];
            stride = 18;
        } else {
            int b = q - 20;
            dst = &sPCr[((b >> 1) * 8) * 18 + (b & 1) * 8 + v];
            stride = 18;
        }

        // pass 2 (over x): raw idct values (level shift folded into epilogue)
#pragma unroll
        for (int u = 0; u < 8; u++) {
            float acc = c0 * CM[0][u];
            acc = fmaf(c1, CM[1][u], acc);
            acc = fmaf(c2, CM[2][u], acc);
            acc = fmaf(c3, CM[3][u], acc);
            acc = fmaf(c4, CM[4][u], acc);
            acc = fmaf(c5, CM[5][u], acc);
            acc = fmaf(c6, CM[6][u], acc);
            acc = fmaf(c7, CM[7][u], acc);
            dst[u * stride] = acc;
        }
    }
    __syncthreads();

    // ---- epilogue: 4 px per thread, vectorized LDS, folded transform ----
    const int py = tid >> 3;           // 0..31
    const int px0 = (tid & 7) * 4;     // 0,4,...,28

    const float M0 = sM[0], M1 = sM[1], M2 = sM[2];
    const float M3 = sM[3], M4 = sM[4], M5 = sM[5];
    const float M6 = sM[6], M7 = sM[7], M8 = sM[8];
    const float K0 = sK[0], K1 = sK[1], K2 = sK[2];

    const int cy = py >> 1, cxb = px0 >> 1;
    float2 cbv = *(const float2*)&sPCb[cy * 18 + cxb];
    float2 crv = *(const float2*)&sPCr[cy * 18 + cxb];
    float4 yv = *(const float4*)&sPY[py * 32 + px0];

    float bR[2], bG[2], bB[2];
    bR[0] = fmaf(cbv.x, M3, fmaf(crv.x, M6, K0));
    bG[0] = fmaf(cbv.x, M4, fmaf(crv.x, M7, K1));
    bB[0] = fmaf(cbv.x, M5, fmaf(crv.x, M8, K2));
    bR[1] = fmaf(cbv.y, M3, fmaf(crv.y, M6, K0));
    bG[1] = fmaf(cbv.y, M4, fmaf(crv.y, M7, K1));
    bB[1] = fmaf(cbv.y, M5, fmaf(crv.y, M8, K2));

    float4 oR, oG, oB;
    oR.x = __saturatef(fmaf(yv.x, M0, bR[0]));
    oG.x = __saturatef(fmaf(yv.x, M1, bG[0]));
    oB.x = __saturatef(fmaf(yv.x, M2, bB[0]));
    oR.y = __saturatef(fmaf(yv.y, M0, bR[0]));
    oG.y = __saturatef(fmaf(yv.y, M1, bG[0]));
    oB.y = __saturatef(fmaf(yv.y, M2, bB[0]));
    oR.z = __saturatef(fmaf(yv.z, M0, bR[1]));
    oG.z = __saturatef(fmaf(yv.z, M1, bG[1]));
    oB.z = __saturatef(fmaf(yv.z, M2, bB[1]));
    oR.w = __saturatef(fmaf(yv.w, M0, bR[1]));
    oG.w = __saturatef(fmaf(yv.w, M1, bG[1]));
    oB.w = __saturatef(fmaf(yv.w, M2, bB[1]));

    const unsigned gy = ty * 32 + py;
    const unsigned gx = tx * 32 + px0;
    const unsigned planeOff = gy * WW + gx;          // fits in u32
    const unsigned base = bz * 3u * (HH * WW);
    __stcs((float4*)(out + base + planeOff), oR);
    __stcs((float4*)(out + base + (HH * WW) + planeOff), oG);
    __stcs((float4*)(out + base + 2u * (HH * WW) + planeOff), oB);
}

extern "C" void kernel_launch(void* const* d_in, const int* in_sizes, int n_in,
                              void* d_out, int out_size) {
    const float* y      = (const float*)d_in[0];
    const float* cb     = (const float*)d_in[1];
    const float* cr     = (const float*)d_in[2];
    const float* ytab   = (const float*)d_in[3];
    const float* ctab   = (const float*)d_in[4];
    const float* alpha  = (const float*)d_in[5];
    // d_in[6] = dct_tensor (unused; cosine basis hard-coded)
    const float* shift  = (const float*)d_in[7];
    const float* matrix = (const float*)d_in[8];
    const int* factor   = (const int*)d_in[11];

    int B = in_sizes[0] / (2048 * 2048);
    if (B < 1) B = 1;

    dim3 grid(WW / 32, HH / 32, B);
    jpeg_decode_kernel<<<grid, 256>>>(y, cb, cr, ytab, ctab, alpha, shift,
                                      matrix, factor, (float*)d_out);
}